// round 7
// baseline (speedup 1.0000x reference)
#include <cuda_runtime.h>
#include <cstdint>

// Problem constants
#define BB 8
#define NN 16
#define SS 118
#define AA 10
#define DD 128      // S + A
#define DKK 64
#define HH 2

// Scratch (no allocations allowed)
__device__ float g_base[BB*HH*NN*DKK];   // base[b,h,i,e]
__device__ float g_diff[BB*HH*NN*DKK];   // (avP-avA)[b,h,j,e]
__device__ float g_C[BB*NN*NN*64];       // C[(b,i,j), n] = sum_he W1[n,he]*nm

// ---------------------------------------------------------------------------
// Threefry2x32 with key = PRNGKey(42) = (0, 42). ks0=0 adds folded out.
// ---------------------------------------------------------------------------
__device__ __forceinline__ void threefry(uint32_t c0, uint32_t c1,
                                         uint32_t& o0, uint32_t& o1) {
  const uint32_t ks1 = 42u;
  const uint32_t ks2 = 42u ^ 0x1BD11BDAu;
  uint32_t x0 = c0;          // + ks0 (=0)
  uint32_t x1 = c1 + ks1;
#define TFR(r) { x0 += x1; x1 = __funnelshift_l(x1, x1, (r)); x1 ^= x0; }
  TFR(13) TFR(15) TFR(26) TFR(6)   x0 += ks1; x1 += ks2 + 1u;
  TFR(17) TFR(29) TFR(16) TFR(24)  x0 += ks2; x1 += 2u;          // + ks0
  TFR(13) TFR(15) TFR(26) TFR(6)   /* x0 += ks0 */ x1 += ks1 + 3u;
  TFR(17) TFR(29) TFR(16) TFR(24)  x0 += ks1; x1 += ks2 + 4u;
  TFR(13) TFR(15) TFR(26) TFR(6)   x0 += ks2; x1 += 5u;          // + ks0
#undef TFR
  o0 = x0; o1 = x1;
}

// Partitionable-threefry 32-bit draw (idx < 2^32 => c0 = 0); bits = o0 ^ o1.
__device__ __forceinline__ float tf_unif(uint32_t idx) {
  uint32_t o0, o1;
  threefry(0u, idx, o0, o1);
  uint32_t bits = o0 ^ o1;
  return __uint_as_float((bits >> 9) | 0x3f800000u);   // in [1,2)
}

// ---------------------------------------------------------------------------
// Stage 1: blocks 0..7    -> attention math per batch b
//          blocks 8..519  -> noise + fused W1-reduction to g_C
// One static smem array (35KB) shared by both code paths.
// ---------------------------------------------------------------------------
__global__ void __launch_bounds__(256) k_stage1(
    const float* __restrict__ states, const float* __restrict__ policies,
    const float* __restrict__ actions, const float* __restrict__ Wk,
    const float* __restrict__ Wq, const float* __restrict__ Wv,
    const float* __restrict__ W1, float* __restrict__ out)
{
  int tid = threadIdx.x;
  __shared__ float sm[8768];               // 35 KB, unioned across paths

  if (blockIdx.x >= 8) {
    // ------------- noise + fused C reduction -------------
    // block handles 4 super-units su=(b,i,j); 128 threads (t=(h,e)) per su-pair
    float (*w1s)[129] = (float (*)[129])sm;            // [64][129]
    float (*nms)[128] = (float (*)[128])(sm + 8256);   // [4][128]
    int bk = blockIdx.x - 8;                           // 0..511

    for (int idx = tid; idx < 8192; idx += 256)
      w1s[idx >> 7][idx & 127] = W1[idx];

    int hb = tid >> 7, tt = tid & 127, h = tt >> 6, e = tt & 63;
#pragma unroll
    for (int s = 0; s < 2; ++s) {
      int su = bk * 4 + hb * 2 + s;                    // 0..2047
      int b = su >> 8, i = (su >> 4) & 15, j = su & 15;
      int unit = ((b * 2 + h) * 16 + i) * 16 + j;
      uint32_t cbase = (uint32_t)unit * 1024u + (uint32_t)e;
      float acc = 0.f;
#pragma unroll 4
      for (int k = 0; k < 16; ++k)
        acc += tf_unif(cbase + (uint32_t)(k * 64));
      // mean((u-0.5)*0.1) = (mean(f) - 1.5)*0.1, f in [1,2)
      nms[hb * 2 + s][tt] = (acc * 0.0625f - 1.5f) * 0.1f;
    }
    __syncthreads();

    // C[su, n] = sum_he W1[n,he] * nm[su,he]  (one output per thread)
    int s4 = tid >> 6, n = tid & 63;
    float c = 0.f;
#pragma unroll 8
    for (int he = 0; he < 128; ++he)
      c += w1s[n][he] * nms[s4][he];     // w1s conflict-free, nms broadcast
    g_C[(bk * 4 + s4) * 64 + n] = c;
    return;
  }

  // ---------------- attention math for batch b ----------------
  int b = blockIdx.x;
  float (*oa)[DD]        = (float (*)[DD])(sm);            // [16][128]
  float (*op)[DD]        = (float (*)[DD])(sm + 2048);     // [16][128]
  float (*kbuf)[NN][DKK] = (float (*)[NN][DKK])(sm + 4096);// [2][16][64]
  float (*qT)[DKK][NN]   = (float (*)[DKK][NN])(sm + 6144);// [2][64][16]
  float (*avA)[NN][DKK]  = (float (*)[NN][DKK])(sm + 6144);// union with qT
  float (*wsm)[NN][NN]   = (float (*)[NN][NN])(sm + 8192); // [2][16][16]

  for (int idx = tid; idx < NN * DD; idx += 256) {
    int n = idx >> 7, d = idx & 127;
    float oav, opv;
    if (d < SS) { float s = states[(b * NN + n) * SS + d]; oav = s; opv = s; }
    else {
      oav = actions [(b * NN + n) * AA + (d - SS)];
      opv = policies[(b * NN + n) * AA + (d - SS)];
    }
    oa[n][d] = oav; op[n][d] = opv;
  }
  __syncthreads();

  int e  = tid & 63;   // output feature
  int ng = tid >> 6;   // row group 0..3

  // K and Q projections
  for (int h = 0; h < 2; ++h) {
    const float4* wk4 = (const float4*)(Wk + (h * 64 + e) * 128);
    const float4* wq4 = (const float4*)(Wq + (h * 64 + e) * 128);
    float sk[4] = {0,0,0,0}, sq[4] = {0,0,0,0};
#pragma unroll 8
    for (int d4 = 0; d4 < 32; ++d4) {
      float4 wkv = wk4[d4];
      float4 wqv = wq4[d4];
#pragma unroll
      for (int t = 0; t < 4; ++t) {
        int n = ng * 4 + t;
        float4 a = *(const float4*)&oa[n][d4 * 4];
        sk[t] += a.x * wkv.x + a.y * wkv.y + a.z * wkv.z + a.w * wkv.w;
        sq[t] += a.x * wqv.x + a.y * wqv.y + a.z * wqv.z + a.w * wqv.w;
      }
    }
#pragma unroll
    for (int t = 0; t < 4; ++t) {
      int n = ng * 4 + t;
      kbuf[h][n][e] = sk[t];
      qT[h][e][n]   = sq[t];
    }
  }
  __syncthreads();

  // scores[b,h,i,j] = q[b,h,j] . k[b,h,i] / sqrt(64)
  for (int o = tid; o < 512; o += 256) {
    int h = o >> 8, i = (o >> 4) & 15, j = o & 15;
    float s = 0.f;
#pragma unroll 16
    for (int ee = 0; ee < 64; ++ee)
      s += qT[h][ee][j] * kbuf[h][i][ee];
    wsm[h][i][j] = s * 0.125f;
  }
  __syncthreads();            // qT dead after this point

  // softmax over j
  if (tid < 32) {
    int h = tid >> 4, i = tid & 15;
    float m = -1e30f;
#pragma unroll
    for (int j = 0; j < 16; ++j) m = fmaxf(m, wsm[h][i][j]);
    float sum = 0.f, ex[16];
#pragma unroll
    for (int j = 0; j < 16; ++j) { ex[j] = expf(wsm[h][i][j] - m); sum += ex[j]; }
    float inv = 1.f / sum;
#pragma unroll
    for (int j = 0; j < 16; ++j) {
      float w = ex[j] * inv;
      wsm[h][i][j] = w;
      out[2048 + ((b * 2 + h) * 16 + i) * 16 + j] = w;   // weight output
    }
  }
  __syncthreads();

  // value projections: avA (aliases qT) = tanh(oa.Wv); diff -> gmem
  for (int h = 0; h < 2; ++h) {
    const float4* wv4 = (const float4*)(Wv + (h * 64 + e) * 128);
    float sA[4] = {0,0,0,0}, sP[4] = {0,0,0,0};
#pragma unroll 8
    for (int d4 = 0; d4 < 32; ++d4) {
      float4 w = wv4[d4];
#pragma unroll
      for (int t = 0; t < 4; ++t) {
        int n = ng * 4 + t;
        float4 a = *(const float4*)&oa[n][d4 * 4];
        float4 p = *(const float4*)&op[n][d4 * 4];
        sA[t] += a.x * w.x + a.y * w.y + a.z * w.z + a.w * w.w;
        sP[t] += p.x * w.x + p.y * w.y + p.z * w.z + p.w * w.w;
      }
    }
#pragma unroll
    for (int t = 0; t < 4; ++t) {
      int n = ng * 4 + t;
      float ta = tanhf(sA[t]);
      float tp = tanhf(sP[t]);
      avA[h][n][e] = ta;
      g_diff[((b * 2 + h) * 16 + n) * 64 + e] = tp - ta;
    }
  }
  __syncthreads();

  // base[b,h,i,e] = sum_k w[b,h,i,k] * avA[b,h,k,e]
  for (int o = tid; o < 2048; o += 256) {
    int h = o >> 10, i = (o >> 6) & 15, ee = o & 63;
    float s = 0.f;
#pragma unroll
    for (int k = 0; k < 16; ++k)
      s += wsm[h][i][k] * avA[h][k][ee];
    g_base[((b * 2 + h) * 16 + i) * 64 + ee] = s;
  }
}

// ---------------------------------------------------------------------------
// Final: block per (b,i). y[n] = U[n] + sum_h w*V[h,j,n] + C[n]; lrelu; .W2
//   U[n]     = (1/16) sum_he W1[n,he] base[b,h,i,e]
//   V[h,j,n] = (1/16) sum_e  W1[n,h*64+e] diff[b,h,j,e]
// ---------------------------------------------------------------------------
__global__ void __launch_bounds__(256) k_final(
    const float* __restrict__ W1, const float* __restrict__ W2,
    float* __restrict__ out)
{
  int b = blockIdx.x >> 4, i = blockIdx.x & 15;
  int t = threadIdx.x;

  __shared__ float w1s[64][129];     // 33KB
  __shared__ float dfs[2][16][64];   // diff, later aliased by V (same shape)
  __shared__ float bss[128];
  __shared__ float Us[64];
  __shared__ float ws[2][16];
  __shared__ float w2s[64];
  float (*Vs)[16][64] = dfs;         // V overwrites diff after sync

  for (int idx = t; idx < 8192; idx += 256)
    w1s[idx >> 7][idx & 127] = W1[idx];
  for (int idx = t; idx < 2048; idx += 256) {
    int h = idx >> 10, j = (idx >> 6) & 15, e = idx & 63;
    dfs[h][j][e] = g_diff[((b * 2 + h) * 16 + j) * 64 + e];
  }
  if (t < 128) {
    int h = t >> 6, e = t & 63;
    bss[t] = g_base[((b * 2 + h) * 16 + i) * 64 + e];
  }
  if (t >= 128 && t < 160) {
    int h = (t - 128) >> 4, j = t & 15;
    ws[h][j] = out[2048 + ((b * 2 + h) * 16 + i) * 16 + j];
  }
  if (t >= 160 && t < 224) w2s[t - 160] = W2[t - 160];
  __syncthreads();

  // U into regs (t<64), V into regs (8 per thread)
  float u = 0.f;
  if (t < 64) {
#pragma unroll 8
    for (int he = 0; he < 128; ++he) u += w1s[t][he] * bss[he];
    u *= 0.0625f;
  }
  int n = t & 63, g = t >> 6;
  float vv[8];
#pragma unroll
  for (int q = 0; q < 8; ++q) {
    int hj = g * 8 + q, h = hj >> 4, j = hj & 15;
    float v = 0.f;
#pragma unroll 8
    for (int e = 0; e < 64; ++e)
      v += w1s[n][h * 64 + e] * dfs[h][j][e];
    vv[q] = v * 0.0625f;
  }
  __syncthreads();                   // all diff reads done
  if (t < 64) Us[t] = u;
#pragma unroll
  for (int q = 0; q < 8; ++q) {
    int hj = g * 8 + q;
    Vs[hj >> 4][hj & 15][n] = vv[q];
  }
  __syncthreads();

  // assemble + lrelu + W2-reduce: warp wp -> j pair, lane -> n, n+32
  int wp = t >> 5, lane = t & 31;
  const float* Cb = g_C + ((b * 16 + i) * 16) * 64;
#pragma unroll
  for (int jj = 0; jj < 2; ++jj) {
    int j = wp * 2 + jj;
    float r = 0.f;
#pragma unroll
    for (int nn = 0; nn < 2; ++nn) {
      int nId = lane + nn * 32;
      float y = Us[nId] + ws[0][j] * Vs[0][j][nId]
                        + ws[1][j] * Vs[1][j][nId] + Cb[j * 64 + nId];
      y = y > 0.f ? y : 0.01f * y;
      r += y * w2s[nId];
    }
#pragma unroll
    for (int o = 16; o > 0; o >>= 1)
      r += __shfl_down_sync(0xffffffffu, r, o);
    if (lane == 0)
      out[(b * 16 + i) * 16 + j] = r;
  }
}

// pads launch count to 3/call so the profiler's capture (observed at kernel
// exec index 3) lands on k_stage1 (first kernel of the second call).
__global__ void k_nop() {}

// ---------------------------------------------------------------------------
extern "C" void kernel_launch(void* const* d_in, const int* in_sizes, int n_in,
                              void* d_out, int out_size) {
  const float* states   = (const float*)d_in[0];
  const float* policies = (const float*)d_in[1];
  const float* actions  = (const float*)d_in[2];
  const float* Wk       = (const float*)d_in[3];
  const float* Wq       = (const float*)d_in[4];
  const float* Wv       = (const float*)d_in[5];
  const float* W1       = (const float*)d_in[6];
  const float* W2       = (const float*)d_in[7];
  float* out = (float*)d_out;

  k_stage1<<<8 + 512, 256>>>(states, policies, actions, Wk, Wq, Wv, W1, out);
  k_final<<<128, 256>>>(W1, W2, out);
  k_nop<<<1, 32>>>();
}

// round 8
// speedup vs baseline: 1.6054x; 1.6054x over previous
#include <cuda_runtime.h>
#include <cstdint>

// Problem constants
#define BB 8
#define NN 16
#define SS 118
#define AA 10
#define DD 128      // S + A
#define DKK 64
#define HH 2

// Scratch (no allocations allowed)
__device__ float g_base[BB*HH*NN*DKK];   // base[b,h,i,e]
__device__ float g_diff[BB*HH*NN*DKK];   // (avP-avA)[b,h,j,e]
__device__ float g_nm[BB*HH*NN*NN*DKK];  // mean_k noise[b,h,i,j,k,e]

// ---------------------------------------------------------------------------
// Threefry2x32 with key = PRNGKey(42) = (0, 42). ks0=0 adds folded out.
// ---------------------------------------------------------------------------
__device__ __forceinline__ void threefry(uint32_t c0, uint32_t c1,
                                         uint32_t& o0, uint32_t& o1) {
  const uint32_t ks1 = 42u;
  const uint32_t ks2 = 42u ^ 0x1BD11BDAu;
  uint32_t x0 = c0;          // + ks0 (=0)
  uint32_t x1 = c1 + ks1;
#define TFR(r) { x0 += x1; x1 = __funnelshift_l(x1, x1, (r)); x1 ^= x0; }
  TFR(13) TFR(15) TFR(26) TFR(6)   x0 += ks1; x1 += ks2 + 1u;
  TFR(17) TFR(29) TFR(16) TFR(24)  x0 += ks2; x1 += 2u;          // + ks0
  TFR(13) TFR(15) TFR(26) TFR(6)   /* x0 += ks0 */ x1 += ks1 + 3u;
  TFR(17) TFR(29) TFR(16) TFR(24)  x0 += ks1; x1 += ks2 + 4u;
  TFR(13) TFR(15) TFR(26) TFR(6)   x0 += ks2; x1 += 5u;          // + ks0
#undef TFR
  o0 = x0; o1 = x1;
}

// Partitionable-threefry 32-bit draw (idx < 2^32 => c0 = 0); bits = o0 ^ o1.
__device__ __forceinline__ float tf_unif(uint32_t idx) {
  uint32_t o0, o1;
  threefry(0u, idx, o0, o1);
  uint32_t bits = o0 ^ o1;
  return __uint_as_float((bits >> 9) | 0x3f800000u);   // in [1,2)
}

// ---------------------------------------------------------------------------
// Stage 1: blocks 0..15     -> attention math per (b,h)
//          blocks 16..1039  -> noise: 1 unit (16 hashes) per thread
// ---------------------------------------------------------------------------
__global__ void __launch_bounds__(256, 6) k_stage1(
    const float* __restrict__ states, const float* __restrict__ policies,
    const float* __restrict__ actions, const float* __restrict__ Wk,
    const float* __restrict__ Wq, const float* __restrict__ Wv,
    float* __restrict__ out)
{
  int tid = threadIdx.x;

  if (blockIdx.x >= 16) {
    // ---------------- noise mean over k ----------------
    int g = (blockIdx.x - 16) * 256 + tid;   // 0..262143
    int e = g & 63;
    int u = g >> 6;                          // unit 0..4095 = (b,h,i,j)
    uint32_t base = (uint32_t)u * 1024u + (uint32_t)e;
    float s = 0.f;
#pragma unroll 2
    for (int k2 = 0; k2 < 8; ++k2) {         // 2 chains in flight (x unroll 2)
      float f0 = tf_unif(base + (uint32_t)(k2 * 128));
      float f1 = tf_unif(base + (uint32_t)(k2 * 128 + 64));
      s += f0 + f1;
    }
    // mean((f-1.5)*0.1), f in [1,2)
    g_nm[u * 64 + e] = (s * 0.0625f - 1.5f) * 0.1f;
    return;
  }

  // ---------------- attention math for (b,h) ----------------
  int b = blockIdx.x >> 1, h = blockIdx.x & 1;
  __shared__ float oa[NN][DD];     // concat(state, action)
  __shared__ float op[NN][DD];     // concat(state, policy)
  __shared__ float kb[NN][DKK];    // k[i][e]
  __shared__ float qT[DKK][NN];    // q transposed [e][j]
  __shared__ float av[NN][DKK];    // tanh(oa.Wv)
  __shared__ float wsm[NN][NN];    // softmax weights

  for (int idx = tid; idx < NN * DD; idx += 256) {
    int n = idx >> 7, d = idx & 127;
    float oav, opv;
    if (d < SS) { float s = states[(b * NN + n) * SS + d]; oav = s; opv = s; }
    else {
      oav = actions [(b * NN + n) * AA + (d - SS)];
      opv = policies[(b * NN + n) * AA + (d - SS)];
    }
    oa[n][d] = oav; op[n][d] = opv;
  }
  __syncthreads();

  int e  = tid & 63;   // output feature
  int ng = tid >> 6;   // row group 0..3 (rows ng*4..ng*4+3)

  // K projection (pass 1) then Q (pass 2) — low register pressure
  {
    const float4* wk4 = (const float4*)(Wk + (h * 64 + e) * 128);
    float sk[4] = {0,0,0,0};
#pragma unroll 8
    for (int d4 = 0; d4 < 32; ++d4) {
      float4 w = wk4[d4];
#pragma unroll
      for (int t = 0; t < 4; ++t) {
        float4 a = *(const float4*)&oa[ng * 4 + t][d4 * 4];
        sk[t] += a.x * w.x + a.y * w.y + a.z * w.z + a.w * w.w;
      }
    }
#pragma unroll
    for (int t = 0; t < 4; ++t) kb[ng * 4 + t][e] = sk[t];
  }
  {
    const float4* wq4 = (const float4*)(Wq + (h * 64 + e) * 128);
    float sq[4] = {0,0,0,0};
#pragma unroll 8
    for (int d4 = 0; d4 < 32; ++d4) {
      float4 w = wq4[d4];
#pragma unroll
      for (int t = 0; t < 4; ++t) {
        float4 a = *(const float4*)&oa[ng * 4 + t][d4 * 4];
        sq[t] += a.x * w.x + a.y * w.y + a.z * w.z + a.w * w.w;
      }
    }
#pragma unroll
    for (int t = 0; t < 4; ++t) qT[e][ng * 4 + t] = sq[t];
  }
  __syncthreads();

  // scores + parallel softmax: thread (i,j), rows = 16-lane shfl groups
  {
    int i = tid >> 4, j = tid & 15;
    float s = 0.f;
#pragma unroll 16
    for (int ee = 0; ee < 64; ++ee)
      s += kb[i][ee] * qT[ee][j];
    s *= 0.125f;
    float m = s;
#pragma unroll
    for (int o = 8; o > 0; o >>= 1)
      m = fmaxf(m, __shfl_xor_sync(0xffffffffu, m, o, 16));
    float ex = expf(s - m);
    float sum = ex;
#pragma unroll
    for (int o = 8; o > 0; o >>= 1)
      sum += __shfl_xor_sync(0xffffffffu, sum, o, 16);
    float w = ex / sum;
    wsm[i][j] = w;
    out[2048 + ((b * 2 + h) * 16 + i) * 16 + j] = w;     // weight output
  }
  __syncthreads();

  // value projections: av = tanh(oa.Wv), diff = tanh(op.Wv) - av
  {
    const float4* wv4 = (const float4*)(Wv + (h * 64 + e) * 128);
    float sA[4] = {0,0,0,0}, sP[4] = {0,0,0,0};
#pragma unroll 8
    for (int d4 = 0; d4 < 32; ++d4) {
      float4 w = wv4[d4];
#pragma unroll
      for (int t = 0; t < 4; ++t) {
        int n = ng * 4 + t;
        float4 a = *(const float4*)&oa[n][d4 * 4];
        float4 p = *(const float4*)&op[n][d4 * 4];
        sA[t] += a.x * w.x + a.y * w.y + a.z * w.z + a.w * w.w;
        sP[t] += p.x * w.x + p.y * w.y + p.z * w.z + p.w * w.w;
      }
    }
#pragma unroll
    for (int t = 0; t < 4; ++t) {
      int n = ng * 4 + t;
      float ta = tanhf(sA[t]);
      float tp = tanhf(sP[t]);
      av[n][e] = ta;
      g_diff[((b * 2 + h) * 16 + n) * 64 + e] = tp - ta;
    }
  }
  __syncthreads();

  // base[i,e] = sum_k wsm[i][k] * av[k][e]
  for (int o = tid; o < 1024; o += 256) {
    int i = o >> 6, ee = o & 63;
    float s = 0.f;
#pragma unroll
    for (int k = 0; k < 16; ++k)
      s += wsm[i][k] * av[k][ee];
    g_base[((b * 2 + h) * 16 + i) * 64 + ee] = s;
  }
}

// ---------------------------------------------------------------------------
// Final: block per (b,i,jq). 4 j's per block. x assembled in smem,
// y[j,n] = lrelu(W1[n,:].x[j,:]) * W2[n], reduced over n.
// ---------------------------------------------------------------------------
__global__ void __launch_bounds__(256) k_final(
    const float* __restrict__ W1, const float* __restrict__ W2,
    float* __restrict__ out)
{
  int blk = blockIdx.x;                 // 0..511
  int b = blk >> 6, i = (blk >> 2) & 15, jq = blk & 3;
  int t = threadIdx.x;

  __shared__ float w1s[64][129];        // pitch 129 -> conflict-free
  __shared__ float xs[4][129];
  __shared__ float w2s[64];
  __shared__ float red[8];

  for (int idx = t; idx < 8192; idx += 256)
    w1s[idx >> 7][idx & 127] = W1[idx];
  if (t < 64) w2s[t] = W2[t];

  for (int idx = t; idx < 512; idx += 256) {
    int jj = idx >> 7, hd = idx & 127;
    int j = jq * 4 + jj, h = hd >> 6, e = hd & 63;
    float w  = out[2048 + ((b * 2 + h) * 16 + i) * 16 + j];
    float bs = g_base[((b * 2 + h) * 16 + i) * 64 + e];
    float df = g_diff[((b * 2 + h) * 16 + j) * 64 + e];
    float nm = g_nm[(((b * 2 + h) * 16 + i) * 16 + j) * 64 + e];
    xs[jj][hd] = (bs + w * df) * 0.0625f + nm;
  }
  __syncthreads();

  // thread (jj = t>>6, n = t&63): one 128-dot
  int jj = t >> 6, n = t & 63;
  float y = 0.f;
#pragma unroll 8
  for (int c = 0; c < 128; ++c)
    y += w1s[n][c] * xs[jj][c];     // w1s conflict-free, xs broadcast
  y = y > 0.f ? y : 0.01f * y;      // leaky_relu(0.01)
  y *= w2s[n];
#pragma unroll
  for (int o = 16; o > 0; o >>= 1)
    y += __shfl_down_sync(0xffffffffu, y, o);
  if ((t & 31) == 0) red[t >> 5] = y;
  __syncthreads();
  if (t < 4)
    out[(b * 16 + i) * 16 + jq * 4 + t] = red[t * 2] + red[t * 2 + 1];
}

// pads launch count to 3/call: profiler capture lands at kernel exec index 4
// = k_stage1 (first kernel of the second call) for the stage1 diagnostic.
__global__ void k_nop() {}

// ---------------------------------------------------------------------------
extern "C" void kernel_launch(void* const* d_in, const int* in_sizes, int n_in,
                              void* d_out, int out_size) {
  const float* states   = (const float*)d_in[0];
  const float* policies = (const float*)d_in[1];
  const float* actions  = (const float*)d_in[2];
  const float* Wk       = (const float*)d_in[3];
  const float* Wq       = (const float*)d_in[4];
  const float* Wv       = (const float*)d_in[5];
  const float* W1       = (const float*)d_in[6];
  const float* W2       = (const float*)d_in[7];
  float* out = (float*)d_out;

  // 16 attention blocks + 1024 noise blocks, concurrent
  k_stage1<<<16 + 1024, 256>>>(states, policies, actions, Wk, Wq, Wv, out);
  k_final<<<512, 256>>>(W1, W2, out);
  k_nop<<<1, 32>>>();
}